// round 5
// baseline (speedup 1.0000x reference)
#include <cuda_runtime.h>
#include <cstdint>

// B=8, N=2048, F=D=128
//   H = A_hat @ X ; O = H @ W^T + b ; out = relu(LN(O)*gamma+beta)
//
// Single fused kernel (tcgen05 unavailable: harness targets base sm_103, so
// tensor path is mma.sync.m16n8k8 tf32 / HMMA).
// 256 CTAs (32 row-tiles of 64 x 8 batches), 256 threads, 2 CTAs/SM.
// Warp grid 2(m) x 4(n), warp tile 32x32. X loaded directly (no transpose
// kernel): B fragments read from [k][f] tiles, PAD=136 => conflict-free.

#define BATCH 8
#define NN    2048
#define FF    128

#define ROWS  64            // rows per CTA tile
#define PADA  36            // A stage row pitch (floats): 64 x (32+4)
#define PADX  136           // X stage row pitch (floats): 32 x (128+8)
#define PADH  132           // H / W pitch (floats)

#define ST_X_OFF   9216     // bytes: A tile 64*36*4
#define STAGE_B    26624    // + X tile 32*136*4 = 17408
#define SM_H_OFF   0        // overlay after mainloop: H 64x132x4 = 33792
#define SM_W_OFF   33792    // W 128x132x4 = 67584 (ends 101376 < 106496)
#define SM_PAR_OFF 106496   // bias|gamma|beta 3*512
#define SM_RED_OFF 108032   // 64 rows x 4 warps x {s1,s2} = 2048 B
#define SM_TOTAL   110080

__device__ __forceinline__ uint32_t smem_u32(const void* p) {
    uint32_t a;
    asm("{ .reg .u64 t; cvta.to.shared.u64 t, %1; cvt.u32.u64 %0, t; }" : "=r"(a) : "l"(p));
    return a;
}
__device__ __forceinline__ void cp16(uint32_t dst, const void* src) {
    asm volatile("cp.async.cg.shared.global [%0], [%1], 16;" :: "r"(dst), "l"(src) : "memory");
}
#define CP_COMMIT() asm volatile("cp.async.commit_group;" ::: "memory")

#define MMA_TF32(d, av, bv)                                                     \
    asm volatile("mma.sync.aligned.m16n8k8.row.col.f32.tf32.tf32.f32 "          \
        "{%0,%1,%2,%3}, {%4,%5,%6,%7}, {%8,%9}, {%0,%1,%2,%3};"                 \
        : "+f"((d)[0]), "+f"((d)[1]), "+f"((d)[2]), "+f"((d)[3])                \
        : "r"((av)[0]), "r"((av)[1]), "r"((av)[2]), "r"((av)[3]),               \
          "r"((bv)[0]), "r"((bv)[1]))

__global__ __launch_bounds__(256, 2)
void fused_kernel(const float* __restrict__ A, const float* __restrict__ X,
                  const float* __restrict__ W,
                  const float* __restrict__ bias, const float* __restrict__ gamma,
                  const float* __restrict__ beta, float* __restrict__ out) {
    extern __shared__ char smem[];
    float* sf = (float*)smem;
    const uint32_t sbu = smem_u32(smem);

    const int tid = threadIdx.x;
    const int lid = tid & 31;
    const int wid = tid >> 5;
    const int gp  = lid >> 2;        // 0..7 row within fragment
    const int tg  = lid & 3;         // 0..3 k within fragment
    const int wm  = wid >> 2;        // 0..1 warp row (32 rows each)
    const int wn  = wid & 3;         // 0..3 warp col (32 cols each)
    const int bt      = blockIdx.x >> 5;
    const int rowTile = blockIdx.x & 31;

    const float* Ab = A + (size_t)bt * NN * NN + (size_t)rowTile * ROWS * NN;
    const float* Xb = X + (size_t)bt * NN * FF;

    float acc[2][4][4];
#pragma unroll
    for (int i = 0; i < 2; i++)
#pragma unroll
        for (int j = 0; j < 4; j++)
#pragma unroll
            for (int k = 0; k < 4; k++) acc[i][j][k] = 0.f;

    // ---- pipeline loader: chunk c (32 k-values) -> stage c&3 ----
    auto load_chunk = [&](int c) {
        const int st = c & 3;
        const uint32_t ab = sbu + (uint32_t)st * STAGE_B;
        const uint32_t xb = ab + ST_X_OFF;
        const float* ga = Ab + c * 32;                       // 64 rows x 32 k
        const float* gx = Xb + (size_t)(c * 32) * FF;        // 32 k x 128 f
        // A: 64*8 = 512 float4, 2 per thread
#pragma unroll
        for (int i = 0; i < 2; i++) {
            int id = tid + i * 256;
            int r = id >> 3, q = id & 7;
            cp16(ab + (uint32_t)(r * PADA + q * 4) * 4u, ga + (size_t)r * NN + q * 4);
        }
        // X: 32*32 = 1024 float4, 4 per thread
#pragma unroll
        for (int i = 0; i < 4; i++) {
            int id = tid + i * 256;
            int r = id >> 5, q = id & 31;
            cp16(xb + (uint32_t)(r * PADX + q * 4) * 4u, gx + (size_t)r * FF + q * 4);
        }
        CP_COMMIT();
    };

    load_chunk(0); load_chunk(1); load_chunk(2);

    // ---- GEMM1 mainloop: 64 chunks of k=32 ----
    for (int c = 0; c < 64; c++) {
        const int st = c & 3;
        asm volatile("cp.async.wait_group 2;" ::: "memory");
        __syncthreads();
        if (c + 3 < 64) load_chunk(c + 3); else CP_COMMIT();  // uniform group count

        const uint32_t* sA = (const uint32_t*)(smem + st * STAGE_B);
        const uint32_t* sX = (const uint32_t*)(smem + st * STAGE_B + ST_X_OFF);
#pragma unroll
        for (int k8 = 0; k8 < 4; k8++) {
            const int kb = k8 * 8;
            uint32_t af[2][4], bf[4][2];
#pragma unroll
            for (int mt = 0; mt < 2; mt++) {
                int r0 = wm * 32 + mt * 16 + gp;
                const uint32_t* p0 = sA + r0 * PADA + kb + tg;
                const uint32_t* p1 = sA + (r0 + 8) * PADA + kb + tg;
                af[mt][0] = p0[0]; af[mt][2] = p0[4];
                af[mt][1] = p1[0]; af[mt][3] = p1[4];
            }
#pragma unroll
            for (int nt = 0; nt < 4; nt++) {
                int nc = wn * 32 + nt * 8 + gp;
                const uint32_t* p = sX + (kb + tg) * PADX + nc;
                bf[nt][0] = p[0]; bf[nt][1] = p[4 * PADX];
            }
#pragma unroll
            for (int mt = 0; mt < 2; mt++)
#pragma unroll
                for (int nt = 0; nt < 4; nt++)
                    MMA_TF32(acc[mt][nt], af[mt], bf[nt]);
        }
    }

    asm volatile("cp.async.wait_group 0;" ::: "memory");
    __syncthreads();   // pipe region may be overwritten now

    // ---- H (regs) -> smem [64][132] ----
#pragma unroll
    for (int mt = 0; mt < 2; mt++)
#pragma unroll
        for (int nt = 0; nt < 4; nt++) {
            int r  = wm * 32 + mt * 16 + gp;
            int cc = wn * 32 + nt * 8 + 2 * tg;
            *(float2*)(sf + (size_t)r * PADH + cc) =
                make_float2(acc[mt][nt][0], acc[mt][nt][1]);
            *(float2*)(sf + (size_t)(r + 8) * PADH + cc) =
                make_float2(acc[mt][nt][2], acc[mt][nt][3]);
        }

    // ---- W [128][128] -> smem [128][132] ----
#pragma unroll
    for (int i = 0; i < 16; i++) {
        int id = tid + i * 256;                  // 0..4095 float4
        int d = id >> 5, q = id & 31;
        float4 v = *(const float4*)(W + (size_t)d * FF + q * 4);
        *(float4*)(sf + SM_W_OFF / 4 + (size_t)d * PADH + q * 4) = v;
    }
    if (tid < 128) {
        sf[SM_PAR_OFF / 4 + tid]       = bias[tid];
        sf[SM_PAR_OFF / 4 + 128 + tid] = gamma[tid];
        sf[SM_PAR_OFF / 4 + 256 + tid] = beta[tid];
    }
    __syncthreads();

    // ---- GEMM2: O = H @ W^T  (K = 128) ----
#pragma unroll
    for (int i = 0; i < 2; i++)
#pragma unroll
        for (int j = 0; j < 4; j++)
#pragma unroll
            for (int k = 0; k < 4; k++) acc[i][j][k] = 0.f;

    const uint32_t* sH = (const uint32_t*)(smem);
    const uint32_t* sW = (const uint32_t*)(smem + SM_W_OFF);
#pragma unroll
    for (int k8 = 0; k8 < 16; k8++) {
        const int kb = k8 * 8;
        uint32_t af[2][4], bf[4][2];
#pragma unroll
        for (int mt = 0; mt < 2; mt++) {
            int r0 = wm * 32 + mt * 16 + gp;
            const uint32_t* p0 = sH + r0 * PADH + kb + tg;
            const uint32_t* p1 = sH + (r0 + 8) * PADH + kb + tg;
            af[mt][0] = p0[0]; af[mt][2] = p0[4];
            af[mt][1] = p1[0]; af[mt][3] = p1[4];
        }
#pragma unroll
        for (int nt = 0; nt < 4; nt++) {
            int dd = wn * 32 + nt * 8 + gp;
            const uint32_t* p = sW + dd * PADH + kb + tg;
            bf[nt][0] = p[0]; bf[nt][1] = p[4];
        }
#pragma unroll
        for (int mt = 0; mt < 2; mt++)
#pragma unroll
            for (int nt = 0; nt < 4; nt++)
                MMA_TF32(acc[mt][nt], af[mt], bf[nt]);
    }

    // ---- epilogue: bias + LayerNorm + ReLU ----
    const float* sbias = sf + SM_PAR_OFF / 4;
    const float* sgam  = sbias + 128;
    const float* sbet  = sbias + 256;

    float s1[2][2] = {{0.f, 0.f}, {0.f, 0.f}};
    float s2[2][2] = {{0.f, 0.f}, {0.f, 0.f}};
#pragma unroll
    for (int mt = 0; mt < 2; mt++)
#pragma unroll
        for (int nt = 0; nt < 4; nt++) {
            int cc = wn * 32 + nt * 8 + 2 * tg;
            float b0 = sbias[cc], b1 = sbias[cc + 1];
            float v0 = acc[mt][nt][0] + b0, v1 = acc[mt][nt][1] + b1;
            float v2 = acc[mt][nt][2] + b0, v3 = acc[mt][nt][3] + b1;
            acc[mt][nt][0] = v0; acc[mt][nt][1] = v1;
            acc[mt][nt][2] = v2; acc[mt][nt][3] = v3;
            s1[mt][0] += v0 + v1;           s2[mt][0] += v0 * v0 + v1 * v1;
            s1[mt][1] += v2 + v3;           s2[mt][1] += v2 * v2 + v3 * v3;
        }
    // reduce across the 4 tg lanes (same output row)
#pragma unroll
    for (int mt = 0; mt < 2; mt++)
#pragma unroll
        for (int h = 0; h < 2; h++) {
            s1[mt][h] += __shfl_xor_sync(0xffffffffu, s1[mt][h], 1);
            s1[mt][h] += __shfl_xor_sync(0xffffffffu, s1[mt][h], 2);
            s2[mt][h] += __shfl_xor_sync(0xffffffffu, s2[mt][h], 1);
            s2[mt][h] += __shfl_xor_sync(0xffffffffu, s2[mt][h], 2);
        }
    // cross-warp (wn 0..3) combine via smem
    float* sred = sf + SM_RED_OFF / 4;
    if (tg == 0) {
#pragma unroll
        for (int mt = 0; mt < 2; mt++)
#pragma unroll
            for (int h = 0; h < 2; h++) {
                int r = wm * 32 + mt * 16 + h * 8 + gp;
                sred[r * 8 + wn * 2 + 0] = s1[mt][h];
                sred[r * 8 + wn * 2 + 1] = s2[mt][h];
            }
    }
    __syncthreads();

    float* outBase = out + ((size_t)bt * NN + (size_t)rowTile * ROWS) * FF;
#pragma unroll
    for (int mt = 0; mt < 2; mt++)
#pragma unroll
        for (int h = 0; h < 2; h++) {
            int r = wm * 32 + mt * 16 + h * 8 + gp;
            float S1 = sred[r * 8 + 0] + sred[r * 8 + 2] + sred[r * 8 + 4] + sred[r * 8 + 6];
            float S2 = sred[r * 8 + 1] + sred[r * 8 + 3] + sred[r * 8 + 5] + sred[r * 8 + 7];
            float mean = S1 * (1.0f / 128.0f);
            float var  = S2 * (1.0f / 128.0f) - mean * mean;
            float inv  = rsqrtf(var + 1e-5f);
            float* orow = outBase + (size_t)r * FF;
#pragma unroll
            for (int nt = 0; nt < 4; nt++) {
                int cc = wn * 32 + nt * 8 + 2 * tg;
                float v0 = acc[mt][nt][h * 2 + 0];
                float v1 = acc[mt][nt][h * 2 + 1];
                float o0 = fmaxf((v0 - mean) * inv * sgam[cc]     + sbet[cc],     0.f);
                float o1 = fmaxf((v1 - mean) * inv * sgam[cc + 1] + sbet[cc + 1], 0.f);
                *(float2*)(orow + cc) = make_float2(o0, o1);
            }
        }
}

// ---------------- launch ----------------
extern "C" void kernel_launch(void* const* d_in, const int* in_sizes, int n_in,
                              void* d_out, int out_size) {
    const float* A     = (const float*)d_in[0];   // [8,2048,2048]
    const float* X     = (const float*)d_in[1];   // [8,2048,128]
    const float* W     = (const float*)d_in[2];   // [128,128]
    const float* bias  = (const float*)d_in[3];
    const float* gamma = (const float*)d_in[4];
    const float* beta  = (const float*)d_in[5];
    float* out = (float*)d_out;

    cudaFuncSetAttribute(fused_kernel, cudaFuncAttributeMaxDynamicSharedMemorySize, SM_TOTAL);

    fused_kernel<<<BATCH * (NN / ROWS), 256, SM_TOTAL>>>(A, X, W, bias, gamma, beta, out);
}